// round 1
// baseline (speedup 1.0000x reference)
#include <cuda_runtime.h>
#include <math.h>
#include <math_constants.h>

#define G      128
#define GG     (G * G)
#define GGG    (G * G * G)
#define NL     200000
#define HALF   200.0f
#define DXC    3.125f
// KW^2 = 9*pi ; 2*sigma^2 = 4.5*pi
#define KW2F    ((float)(9.0 * 3.14159265358979323846))
#define INV2S2  ((float)(1.0 / (4.5 * 3.14159265358979323846)))

// Scratch: z-axis needs a transposed copy img_z[k][i][j] = image[i][j][k]
__device__ float g_img_z[GGG];

__global__ void transpose_z_kernel(const float* __restrict__ img) {
    int idx = blockIdx.x * blockDim.x + threadIdx.x;
    if (idx >= GGG) return;
    int j = idx & (G - 1);
    int i = (idx >> 7) & (G - 1);
    int k = idx >> 14;
    g_img_z[idx] = img[i * GG + j * G + k];
}

// One thread per LOR. KSTR/ISTR: strides of slice-k and row-ii in `base`.
// PX,PY,PZ: permutation columns of the 6-float LOR row.
template <int KSTR, int ISTR, int PX, int PY, int PZ>
__global__ void __launch_bounds__(256)
proj_kernel(const float* __restrict__ base,
            const float* __restrict__ lors,
            float* __restrict__ out) {
    int lor = blockIdx.x * blockDim.x + threadIdx.x;
    if (lor >= NL) return;

    const float* l = lors + lor * 6;
    float p0x = l[PX],     p0y = l[PY],     p0z = l[PZ];
    float dvx = l[PX + 3] - p0x;
    float dvy = l[PY + 3] - p0y;
    float dvz = l[PZ + 3] - p0z;

    float L = sqrtf(dvx * dvx + dvy * dvy + dvz * dvz);
    float inv_dzl = 1.0f / dvz;
    float path = DXC * L / fabsf(dvz);

    float acc = 0.0f;

    for (int k = 0; k < G; k++) {
        float zc = -HALF + ((float)k + 0.5f) * DXC;
        float t  = (zc - p0z) * inv_dzl;
        float xc = fmaf(t, dvx, p0x);
        float yc = fmaf(t, dvy, p0y);

        int i0 = (int)floorf((xc + HALF) / DXC);
        int j0 = (int)floorf((yc + HALF) / DXC);

        float wx[5], wyv[5], dx2[5], dy2[5];
        int   jc[5];

        #pragma unroll
        for (int a = 0; a < 5; a++) {
            int ii = i0 + a - 2;
            float xi = ((float)ii + 0.5f) * DXC - HALF;   // xmin + (ii+0.5)*dx
            float d  = xi - xc;
            dx2[a]   = d * d;
            wx[a]    = ((unsigned)ii < (unsigned)G) ? __expf(-dx2[a] * INV2S2) : 0.0f;
        }
        #pragma unroll
        for (int b = 0; b < 5; b++) {
            int jj = j0 + b - 2;
            float yj = ((float)jj + 0.5f) * DXC - HALF;
            float d  = yj - yc;
            dy2[b]   = d * d;
            wyv[b]   = ((unsigned)jj < (unsigned)G) ? __expf(-dy2[b] * INV2S2) : 0.0f;
            jc[b]    = min(max(jj, 0), G - 1);
        }

        float valid = (t >= 0.0f && t <= 1.0f) ? 1.0f : 0.0f;

        const float* kbase = base + (size_t)k * KSTR;
        float s = 0.0f;
        #pragma unroll
        for (int a = 0; a < 5; a++) {
            int ii = min(max(i0 + a - 2, 0), G - 1);
            const float* row = kbase + (size_t)ii * ISTR;
            float rs = 0.0f;
            #pragma unroll
            for (int b = 0; b < 5; b++) {
                float d2 = dx2[a] + dy2[b];
                float w  = (d2 <= KW2F) ? wyv[b] : 0.0f;
                rs = fmaf(w, __ldg(row + jc[b]), rs);
            }
            s = fmaf(wx[a], rs, s);
        }
        acc = fmaf(s, valid, acc);
    }

    out[lor] = acc * path;
}

extern "C" void kernel_launch(void* const* d_in, const int* in_sizes, int n_in,
                              void* d_out, int out_size) {
    const float* image = (const float*)d_in[0];
    const float* xlors = (const float*)d_in[1];
    const float* ylors = (const float*)d_in[2];
    const float* zlors = (const float*)d_in[3];
    float* out = (float*)d_out;

    // Build z-transposed image copy in device scratch
    transpose_z_kernel<<<(GGG + 255) / 256, 256>>>(image);

    float* img_z_ptr = nullptr;
    cudaGetSymbolAddress((void**)&img_z_ptr, g_img_z);

    const int blocks = (NL + 255) / 256;

    // axis x: perm [1,2,0]; slice k: image[k][ii][jj] -> KSTR=GG, ISTR=G
    proj_kernel<GG, G, 1, 2, 0><<<blocks, 256>>>(image, xlors, out + 0 * NL);
    // axis y: perm [0,2,1]; slice k: image[ii][k][jj] -> KSTR=G, ISTR=GG
    proj_kernel<G, GG, 0, 2, 1><<<blocks, 256>>>(image, ylors, out + 1 * NL);
    // axis z: perm [0,1,2]; transposed copy img_z[k][ii][jj] -> KSTR=GG, ISTR=G
    proj_kernel<GG, G, 0, 1, 2><<<blocks, 256>>>(img_z_ptr, zlors, out + 2 * NL);
}

// round 2
// speedup vs baseline: 1.7479x; 1.7479x over previous
#include <cuda_runtime.h>
#include <math.h>

#define G       128
#define GG      16384
#define GGG     2097152
#define NL      200000
#define HALF    200.0f
#define DXC     3.125f
#define INV_DXC 0.32f
#define KW2F    28.274333882308138f        /* 9*pi */
#define INV2S2  0.070735530263064588f      /* 1/(4.5*pi) */

// z-axis needs a transposed copy img_z[k][i][j] = image[i][j][k]
__device__ float g_img_z[GGG];

__global__ void transpose_z_kernel(const float* __restrict__ img) {
    int idx = blockIdx.x * blockDim.x + threadIdx.x;
    if (idx >= GGG) return;
    int j = idx & (G - 1);
    int i = (idx >> 7) & (G - 1);
    int k = idx >> 14;
    g_img_z[idx] = img[i * GG + j * G + k];
}

// One LOR projection. KSTR/ISTR: strides of slice-k and row-ii.
// PX,PY,PZ: permutation columns of the 6-float LOR row.
template <int KSTR, int ISTR, int PX, int PY, int PZ>
__device__ __forceinline__ float project_one(const float* __restrict__ base,
                                             const float* __restrict__ l,
                                             float Qc) {
    float p0x = l[PX], p0y = l[PY], p0z = l[PZ];
    float dvx = l[PX + 3] - p0x;
    float dvy = l[PY + 3] - p0y;
    float dvz = l[PZ + 3] - p0z;

    float L = sqrtf(dvx * dvx + dvy * dvy + dvz * dvz);
    float inv_dzl = 1.0f / dvz;
    float path = DXC * L / fabsf(dvz);

    float acc = 0.0f;

    for (int k = 0; k < G; k++) {
        float zc = fmaf((float)k, DXC, 0.5f * DXC - HALF);
        float t  = (zc - p0z) * inv_dzl;
        float xc = fmaf(t, dvx, p0x);
        float yc = fmaf(t, dvy, p0y);

        int i0 = __float2int_rd((xc + HALF) * INV_DXC);
        int j0 = __float2int_rd((yc + HALF) * INV_DXC);

        // Aligned 8-wide j-window [aj, aj+7] always covers every cell inside
        // the cutoff radius (1.70 cells) and is always fully in [0,127].
        int aj = (j0 - 2) & ~3;
        aj = max(0, min(120, aj));

        float dy0 = fmaf((float)aj + 0.5f, DXC, -HALF) - yc;

        // Gaussian weights along j via geometric recurrence: 2 EX2 instead of 8.
        float w = __expf(-dy0 * dy0 * INV2S2);
        float r = __expf(-INV2S2 * fmaf(2.0f * dy0, DXC, DXC * DXC));
        float wy[8], dy2[8];
        #pragma unroll
        for (int c = 0; c < 8; c++) {
            float d = fmaf((float)c, DXC, dy0);
            dy2[c] = d * d;
            wy[c]  = w;
            w *= r;
            r *= Qc;
        }

        const float* kb = base + k * KSTR + aj;

        float s = 0.0f;
        #pragma unroll
        for (int ar = 0; ar < 5; ar++) {
            int ii = i0 + ar - 2;
            float dxv = fmaf((float)ii + 0.5f, DXC, -HALF) - xc;
            float dx2 = dxv * dxv;
            float wxv = ((unsigned)ii < (unsigned)G) ? __expf(-dx2 * INV2S2) : 0.0f;
            int iic = min(max(ii, 0), G - 1);

            const float4* rp = (const float4*)(kb + iic * ISTR);
            float4 q0 = __ldg(rp);
            float4 q1 = __ldg(rp + 1);

            float thr = KW2F - dx2;   // pair passes iff dy2[c] <= thr  (== d2 <= KW2)
            float rs;
            rs =      ((dy2[0] <= thr) ? wy[0] : 0.0f) * q0.x;
            rs = fmaf(((dy2[1] <= thr) ? wy[1] : 0.0f), q0.y, rs);
            rs = fmaf(((dy2[2] <= thr) ? wy[2] : 0.0f), q0.z, rs);
            rs = fmaf(((dy2[3] <= thr) ? wy[3] : 0.0f), q0.w, rs);
            rs = fmaf(((dy2[4] <= thr) ? wy[4] : 0.0f), q1.x, rs);
            rs = fmaf(((dy2[5] <= thr) ? wy[5] : 0.0f), q1.y, rs);
            rs = fmaf(((dy2[6] <= thr) ? wy[6] : 0.0f), q1.z, rs);
            rs = fmaf(((dy2[7] <= thr) ? wy[7] : 0.0f), q1.w, rs);

            s = fmaf(wxv, rs, s);
        }
        acc += s;   // t is always in (0,1) by construction (axis coord = +/-half)
    }
    return acc * path;
}

__global__ void __launch_bounds__(256, 4)
fused_proj(const float* __restrict__ img,
           const float* __restrict__ xl,
           const float* __restrict__ yl,
           const float* __restrict__ zl,
           float* __restrict__ out) {
    const float Qc = __expf(-2.0f * INV2S2 * DXC * DXC);
    int stride = gridDim.x * blockDim.x;
    for (int idx = blockIdx.x * blockDim.x + threadIdx.x; idx < 3 * NL; idx += stride) {
        float res;
        if (idx < NL) {
            // axis x: perm [1,2,0]; slice image[k][ii][jj]
            res = project_one<GG, G, 1, 2, 0>(img, xl + idx * 6, Qc);
        } else if (idx < 2 * NL) {
            // axis y: perm [0,2,1]; slice image[ii][k][jj]
            res = project_one<G, GG, 0, 2, 1>(img, yl + (idx - NL) * 6, Qc);
        } else {
            // axis z: transposed copy img_z[k][ii][jj]
            res = project_one<GG, G, 0, 1, 2>(g_img_z, zl + (idx - 2 * NL) * 6, Qc);
        }
        out[idx] = res;
    }
}

extern "C" void kernel_launch(void* const* d_in, const int* in_sizes, int n_in,
                              void* d_out, int out_size) {
    const float* image = (const float*)d_in[0];
    const float* xlors = (const float*)d_in[1];
    const float* ylors = (const float*)d_in[2];
    const float* zlors = (const float*)d_in[3];
    float* out = (float*)d_out;

    transpose_z_kernel<<<(GGG + 255) / 256, 256>>>(image);

    // 4 blocks/SM guaranteed resident (launch_bounds) -> 592 blocks = one wave,
    // grid-stride removes the tail-wave quantization entirely.
    fused_proj<<<592, 256>>>(image, xlors, ylors, zlors, out);
}

// round 3
// speedup vs baseline: 3.7465x; 2.1434x over previous
#include <cuda_runtime.h>
#include <cuda_fp16.h>
#include <math.h>

#define G       128
#define GG      16384
#define GGG     2097152
#define NL      200000
#define HALF_W  200.0f
#define DXC     3.125f
#define INV_DXC 0.32f
#define KW2F    28.274333882308138f        /* 9*pi */
#define INV2S2  0.070735530263064588f      /* 1/(4.5*pi) */

// fp16 image copies. A: normal layout (serves x & y axes). B: j-shifted by 4.
// Az/Bz: z-transposed layout [k][i][j] = image[i][j][k], and its j-shift.
__device__ __half g_A [GGG];
__device__ __half g_B [GGG];
__device__ __half g_Az[GGG];
__device__ __half g_Bz[GGG];

__global__ void build_half_xy(const float* __restrict__ img) {
    int idx = blockIdx.x * blockDim.x + threadIdx.x;
    if (idx >= GGG) return;
    int j = idx & (G - 1);
    g_A[idx] = __float2half(img[idx]);
    g_B[idx] = (j + 4 < G) ? __float2half(img[idx + 4]) : __float2half(0.0f);
}

__global__ void build_half_z(const float* __restrict__ img) {
    int idx = blockIdx.x * blockDim.x + threadIdx.x;
    if (idx >= GGG) return;
    int j = idx & (G - 1);
    int i = (idx >> 7) & (G - 1);
    int k = idx >> 14;
    g_Az[idx] = __float2half(img[i * GG + j * G + k]);
    g_Bz[idx] = (j + 4 < G) ? __float2half(img[i * GG + (j + 4) * G + k])
                            : __float2half(0.0f);
}

// One LOR projection. KSTR/ISTR: strides (in elements) of slice-k and row-ii.
// PX,PY,PZ: permutation columns of the 6-float LOR row.
template <int KSTR, int ISTR, int PX, int PY, int PZ>
__device__ __forceinline__ float project_one(const __half* __restrict__ A,
                                             const __half* __restrict__ B,
                                             const float* __restrict__ l,
                                             float Qc) {
    float p0x = l[PX], p0y = l[PY], p0z = l[PZ];
    float dvx = l[PX + 3] - p0x;
    float dvy = l[PY + 3] - p0y;
    float dvz = l[PZ + 3] - p0z;

    float L = sqrtf(dvx * dvx + dvy * dvy + dvz * dvz);
    float inv_dzl = 1.0f / dvz;
    float path = DXC * L / fabsf(dvz);

    float acc = 0.0f;

    for (int k = 0; k < G; k++) {
        float zc = fmaf((float)k, DXC, 0.5f * DXC - HALF_W);
        float t  = (zc - p0z) * inv_dzl;
        float xc = fmaf(t, dvx, p0x);
        float yc = fmaf(t, dvy, p0y);

        float ux = (xc + HALF_W) * INV_DXC;
        float uy = (yc + HALF_W) * INV_DXC;
        int i0 = __float2int_rd(ux);
        int j0 = __float2int_rd(uy);
        float fx = ux - (float)i0;

        // ---- j window: aligned (4-cell granular) 8-wide, one 16B load per row
        int w = (j0 - 2) & ~3;
        w = max(0, min(120, w));
        // 16B alignment: bit2 of w selects the 4-shifted copy B.
        bool selB = (w & 4) != 0;
        const __half* jb = selB ? (B + (w - 4)) : (A + w);
        jb += k * KSTR;

        float dy0 = fmaf((float)w + 0.5f, DXC, -HALF_W) - yc;
        float wyc = __expf(-dy0 * dy0 * INV2S2);
        float ry  = __expf(-INV2S2 * fmaf(2.0f * dy0, DXC, DXC * DXC));
        float wy[8], dy2[8];
        #pragma unroll
        for (int c = 0; c < 8; c++) {
            float d = fmaf((float)c, DXC, dy0);
            dy2[c] = d * d;
            wy[c]  = wyc;
            wyc *= ry;
            ry  *= Qc;
        }

        // ---- rows: exact 4-row support
        int ir = i0 + ((fx < 0.5f) ? -2 : -1);

        // issue all 4 row loads first (MLP)
        uint4 q[4];
        #pragma unroll
        for (int r = 0; r < 4; r++) {
            int iic = min(max(ir + r, 0), G - 1);
            q[r] = __ldg((const uint4*)(jb + iic * ISTR));
        }

        float dxr = fmaf((float)ir + 0.5f, DXC, -HALF_W) - xc;
        float wxc = __expf(-dxr * dxr * INV2S2);
        float rx  = __expf(-INV2S2 * fmaf(2.0f * dxr, DXC, DXC * DXC));

        float s = 0.0f;
        #pragma unroll
        for (int r = 0; r < 4; r++) {
            int ii = ir + r;
            float d  = fmaf((float)r, DXC, dxr);
            float dx2 = d * d;
            float wxv = ((unsigned)ii < (unsigned)G) ? wxc : 0.0f;
            wxc *= rx;
            rx  *= Qc;

            const __half2* hp = (const __half2*)&q[r];
            float2 v01 = __half22float2(hp[0]);
            float2 v23 = __half22float2(hp[1]);
            float2 v45 = __half22float2(hp[2]);
            float2 v67 = __half22float2(hp[3]);

            float thr = KW2F - dx2;
            float rs;
            rs =      ((dy2[0] <= thr) ? wy[0] : 0.0f) * v01.x;
            rs = fmaf(((dy2[1] <= thr) ? wy[1] : 0.0f), v01.y, rs);
            rs = fmaf(((dy2[2] <= thr) ? wy[2] : 0.0f), v23.x, rs);
            rs = fmaf(((dy2[3] <= thr) ? wy[3] : 0.0f), v23.y, rs);
            rs = fmaf(((dy2[4] <= thr) ? wy[4] : 0.0f), v45.x, rs);
            rs = fmaf(((dy2[5] <= thr) ? wy[5] : 0.0f), v45.y, rs);
            rs = fmaf(((dy2[6] <= thr) ? wy[6] : 0.0f), v67.x, rs);
            rs = fmaf(((dy2[7] <= thr) ? wy[7] : 0.0f), v67.y, rs);

            s = fmaf(wxv, rs, s);
        }
        acc += s;   // t is always in (0,1): axis endpoints are at +/-half
    }
    return acc * path;
}

__global__ void __launch_bounds__(256, 4)
fused_proj(const float* __restrict__ xl,
           const float* __restrict__ yl,
           const float* __restrict__ zl,
           float* __restrict__ out) {
    const float Qc = __expf(-2.0f * INV2S2 * DXC * DXC);
    int stride = gridDim.x * blockDim.x;
    for (int idx = blockIdx.x * blockDim.x + threadIdx.x; idx < 3 * NL; idx += stride) {
        float res;
        if (idx < NL) {
            // axis x: slice A[k][ii][jj]          -> KSTR=GG, ISTR=G
            res = project_one<GG, G, 1, 2, 0>(g_A, g_B, xl + idx * 6, Qc);
        } else if (idx < 2 * NL) {
            // axis y: slice A[ii][k][jj]          -> KSTR=G, ISTR=GG
            res = project_one<G, GG, 0, 2, 1>(g_A, g_B, yl + (idx - NL) * 6, Qc);
        } else {
            // axis z: transposed Az[k][ii][jj]    -> KSTR=GG, ISTR=G
            res = project_one<GG, G, 0, 1, 2>(g_Az, g_Bz, zl + (idx - 2 * NL) * 6, Qc);
        }
        out[idx] = res;
    }
}

extern "C" void kernel_launch(void* const* d_in, const int* in_sizes, int n_in,
                              void* d_out, int out_size) {
    const float* image = (const float*)d_in[0];
    const float* xlors = (const float*)d_in[1];
    const float* ylors = (const float*)d_in[2];
    const float* zlors = (const float*)d_in[3];
    float* out = (float*)d_out;

    build_half_xy<<<(GGG + 255) / 256, 256>>>(image);
    build_half_z <<<(GGG + 255) / 256, 256>>>(image);

    fused_proj<<<592, 256>>>(xlors, ylors, zlors, out);
}